// round 4
// baseline (speedup 1.0000x reference)
#include <cuda_runtime.h>
#include <math.h>

#define NN 50000
#define NE 800000
#define CIN 64
#define KDIM 192   // HID*C_IN
#define COUT 128

// ---- static scratch (no allocations allowed) ----
__device__ int   g_count[2 * NN];
__device__ int   g_start[2 * (NN + 1)];
__device__ int   g_cursor[2 * NN];
__device__ int   g_src_sorted[2 * NE];                  // 6.4 MB
__device__ float g_ea_sorted[(size_t)2 * NE * 6];       // 38.4 MB
__device__ float g_aggr[(size_t)2 * NN * KDIM];         // 76.8 MB

__global__ void zero_counts_kernel() {
    int i = blockIdx.x * blockDim.x + threadIdx.x;
    if (i < 2 * NN) g_count[i] = 0;
}

// edge_index is int32 on device (JAX x64 disabled -> astype(int64) is a no-op)
__global__ void hist_kernel(const int* __restrict__ ei, int layer) {
    int e = blockIdx.x * blockDim.x + threadIdx.x;
    if (e < NE) {
        int dst = ei[NE + e];
        atomicAdd(&g_count[layer * NN + dst], 1);
    }
}

__global__ void scan_kernel() {
    int layer = blockIdx.x;
    const int* cnt = g_count + layer * NN;
    int* start = g_start + layer * (NN + 1);
    int* cur   = g_cursor + layer * NN;

    __shared__ int warp_sums[32];
    __shared__ int s_carry;
    int tid = threadIdx.x;
    if (tid == 0) s_carry = 0;
    __syncthreads();

    for (int base = 0; base < NN; base += 1024) {
        int i = base + tid;
        int v = (i < NN) ? cnt[i] : 0;
        int xs = v;
        #pragma unroll
        for (int o = 1; o < 32; o <<= 1) {
            int y = __shfl_up_sync(0xffffffffu, xs, o);
            if ((tid & 31) >= o) xs += y;
        }
        if ((tid & 31) == 31) warp_sums[tid >> 5] = xs;
        __syncthreads();
        if (tid < 32) {
            int w = warp_sums[tid];
            #pragma unroll
            for (int o = 1; o < 32; o <<= 1) {
                int y = __shfl_up_sync(0xffffffffu, w, o);
                if (tid >= o) w += y;
            }
            warp_sums[tid] = w;
        }
        __syncthreads();
        int incl = xs + s_carry + ((tid >= 32) ? warp_sums[(tid >> 5) - 1] : 0);
        if (i < NN) { start[i] = incl - v; cur[i] = incl - v; }
        __syncthreads();
        if (tid == 1023) s_carry = incl;
        __syncthreads();
    }
    if (tid == 0) start[NN] = s_carry;
}

__global__ void scatter_kernel(const int* __restrict__ ei,
                               const float* __restrict__ eattr, int layer) {
    int e = blockIdx.x * blockDim.x + threadIdx.x;
    if (e >= NE) return;
    int dst = ei[NE + e];
    int pos = atomicAdd(&g_cursor[layer * NN + dst], 1);
    g_src_sorted[layer * NE + pos] = ei[e];
    const float* ea = eattr + (size_t)e * 6;
    float* o = g_ea_sorted + ((size_t)layer * NE + pos) * 6;
    #pragma unroll
    for (int a = 0; a < 6; a++) o[a] = ea[a];
}

// 64 threads per node; thread c owns aggr channels 3c..3c+2
__global__ void __launch_bounds__(256) edge_aggr_kernel(
    const float* __restrict__ x, const float* __restrict__ W_in,
    const float* __restrict__ b_in, int layer)
{
    int node = blockIdx.x * 4 + (threadIdx.x >> 6);
    int c = threadIdx.x & 63;
    if (node >= NN) return;

    float w0[6], w1[6], w2[6];
    #pragma unroll
    for (int a = 0; a < 6; a++) {
        w0[a] = W_in[a * KDIM + 3 * c + 0];
        w1[a] = W_in[a * KDIM + 3 * c + 1];
        w2[a] = W_in[a * KDIM + 3 * c + 2];
    }
    float b0 = b_in[3 * c + 0], b1 = b_in[3 * c + 1], b2 = b_in[3 * c + 2];

    const int* starts = g_start + layer * (NN + 1);
    int s = starts[node], eEnd = starts[node + 1];
    const int*   srcs = g_src_sorted + layer * NE;
    const float* eas  = g_ea_sorted + (size_t)layer * NE * 6;

    float acc0 = 0.f, acc1 = 0.f, acc2 = 0.f;
    for (int i = s; i < eEnd; i++) {
        int srcv = srcs[i];
        const float* ea = eas + (size_t)i * 6;
        float a0 = ea[0], a1 = ea[1], a2 = ea[2], a3 = ea[3], a4 = ea[4], a5 = ea[5];
        float xc = x[srcv * CIN + c];

        float s0 = fmaf(a0, w0[0], b0); s0 = fmaf(a1, w0[1], s0); s0 = fmaf(a2, w0[2], s0);
        s0 = fmaf(a3, w0[3], s0); s0 = fmaf(a4, w0[4], s0); s0 = fmaf(a5, w0[5], s0);
        float s1 = fmaf(a0, w1[0], b1); s1 = fmaf(a1, w1[1], s1); s1 = fmaf(a2, w1[2], s1);
        s1 = fmaf(a3, w1[3], s1); s1 = fmaf(a4, w1[4], s1); s1 = fmaf(a5, w1[5], s1);
        float s2 = fmaf(a0, w2[0], b2); s2 = fmaf(a1, w2[1], s2); s2 = fmaf(a2, w2[2], s2);
        s2 = fmaf(a3, w2[3], s2); s2 = fmaf(a4, w2[4], s2); s2 = fmaf(a5, w2[5], s2);

        s0 = fmaxf(s0, 0.f); s1 = fmaxf(s1, 0.f); s2 = fmaxf(s2, 0.f);
        acc0 = fmaf(s0, xc, acc0);
        acc1 = fmaf(s1, xc, acc1);
        acc2 = fmaf(s2, xc, acc2);
    }

    float* o = g_aggr + ((size_t)layer * NN + node) * KDIM + 3 * c;
    o[0] = acc0; o[1] = acc1; o[2] = acc2;
}

// block: 64 nodes x 128 cols, 256 threads, 8x4 outputs/thread, K in chunks of 32
__global__ void __launch_bounds__(256) gemm_tanh_kernel(
    int layer, const float* __restrict__ Wout,
    const float* __restrict__ bout, float* __restrict__ out)
{
    const float* aggr = g_aggr + (size_t)layer * NN * KDIM;
    __shared__ float As[64][33];
    __shared__ float Bs[32][128];

    int tid = threadIdx.x;
    int tx = tid & 31;
    int ty = tid >> 5;
    int n0 = blockIdx.x * 64;

    float acc[8][4];
    #pragma unroll
    for (int i = 0; i < 8; i++)
        #pragma unroll
        for (int q = 0; q < 4; q++) acc[i][q] = 0.f;

    for (int k0 = 0; k0 < KDIM; k0 += 32) {
        #pragma unroll
        for (int j = 0; j < 8; j++) {
            int idx = tid + 256 * j;
            int r = idx >> 5, kk = idx & 31;
            int n = n0 + r;
            As[r][kk] = (n < NN) ? aggr[(size_t)n * KDIM + k0 + kk] : 0.f;
        }
        #pragma unroll
        for (int j = 0; j < 16; j++) {
            int idx = tid + 256 * j;
            int kk = idx >> 7, cc = idx & 127;
            Bs[kk][cc] = Wout[(k0 + kk) * COUT + cc];
        }
        __syncthreads();
        #pragma unroll
        for (int kk = 0; kk < 32; kk++) {
            float a[8], bb[4];
            #pragma unroll
            for (int i = 0; i < 8; i++) a[i] = As[ty * 8 + i][kk];
            #pragma unroll
            for (int q = 0; q < 4; q++) bb[q] = Bs[kk][tx + 32 * q];
            #pragma unroll
            for (int i = 0; i < 8; i++)
                #pragma unroll
                for (int q = 0; q < 4; q++)
                    acc[i][q] = fmaf(a[i], bb[q], acc[i][q]);
        }
        __syncthreads();
    }

    #pragma unroll
    for (int q = 0; q < 4; q++) {
        int cc = tx + 32 * q;
        float bv = bout[cc];
        #pragma unroll
        for (int i = 0; i < 8; i++) {
            int n = n0 + ty * 8 + i;
            if (n < NN) out[(size_t)n * (2 * COUT) + (size_t)layer * COUT + cc] =
                tanhf(acc[i][q] + bv);
        }
    }
}

extern "C" void kernel_launch(void* const* d_in, const int* in_sizes, int n_in,
                              void* d_out, int out_size) {
    const float* x     = (const float*)d_in[0];
    const int*   ei0   = (const int*)d_in[1];
    const float* ea0   = (const float*)d_in[2];
    const int*   ei1   = (const int*)d_in[3];
    const float* ea1   = (const float*)d_in[4];
    const float* Win0  = (const float*)d_in[5];
    const float* bin0  = (const float*)d_in[6];
    const float* Wout0 = (const float*)d_in[7];
    const float* bout0 = (const float*)d_in[8];
    const float* Win1  = (const float*)d_in[9];
    const float* bin1  = (const float*)d_in[10];
    const float* Wout1 = (const float*)d_in[11];
    const float* bout1 = (const float*)d_in[12];
    float* out = (float*)d_out;
    (void)in_sizes; (void)n_in; (void)out_size;

    zero_counts_kernel<<<(2 * NN + 255) / 256, 256>>>();
    hist_kernel<<<(NE + 255) / 256, 256>>>(ei0, 0);
    hist_kernel<<<(NE + 255) / 256, 256>>>(ei1, 1);
    scan_kernel<<<2, 1024>>>();
    scatter_kernel<<<(NE + 255) / 256, 256>>>(ei0, ea0, 0);
    scatter_kernel<<<(NE + 255) / 256, 256>>>(ei1, ea1, 1);

    edge_aggr_kernel<<<(NN + 3) / 4, 256>>>(x, Win0, bin0, 0);
    edge_aggr_kernel<<<(NN + 3) / 4, 256>>>(x, Win1, bin1, 1);

    gemm_tanh_kernel<<<(NN + 63) / 64, 256>>>(0, Wout0, bout0, out);
    gemm_tanh_kernel<<<(NN + 63) / 64, 256>>>(1, Wout1, bout1, out);
}

// round 6
// speedup vs baseline: 1.4575x; 1.4575x over previous
#include <cuda_runtime.h>
#include <math.h>

#define NN 50000
#define NE 800000
#define CIN 64
#define KDIM 192   // HID*C_IN
#define COUT 128
#define TOTN (2 * NN)
#define TOTE (2 * NE)
#define NB ((TOTN + 1023) / 1024)   // 98 scan blocks

typedef unsigned long long ull;

// ---- static scratch (no allocations allowed) ----
__device__ int   g_count[TOTN];
__device__ int   g_start[TOTN + 1];
__device__ int   g_cursor[TOTN];
__device__ int   g_partial[128];
__device__ int   g_src_sorted[TOTE];                    // 6.4 MB
__device__ float g_ea_sorted[(size_t)TOTE * 6];         // 38.4 MB
__device__ float g_aggr[(size_t)TOTN * KDIM];           // 76.8 MB

// ---------- f32x2 helpers ----------
__device__ __forceinline__ ull pack2(float lo, float hi) {
    ull r; asm("mov.b64 %0, {%1,%2};" : "=l"(r) : "f"(lo), "f"(hi)); return r;
}
__device__ __forceinline__ void unpack2(ull v, float& lo, float& hi) {
    asm("mov.b64 {%0,%1}, %2;" : "=f"(lo), "=f"(hi) : "l"(v));
}
__device__ __forceinline__ void fma2(ull& d, ull a, ull b) {
    asm("fma.rn.f32x2 %0, %1, %2, %0;" : "+l"(d) : "l"(a), "l"(b));
}

// ---------------- CSR build ----------------
__global__ void zero_counts_kernel() {
    int i = blockIdx.x * blockDim.x + threadIdx.x;
    if (i < TOTN) g_count[i] = 0;
}

// edge_index is int32 on device (JAX x64 disabled -> astype(int64) is a no-op)
__global__ void hist_kernel(const int* __restrict__ ei0, const int* __restrict__ ei1) {
    int e = blockIdx.x * blockDim.x + threadIdx.x;
    if (e >= TOTE) return;
    int layer = (e >= NE);
    const int* ei = layer ? ei1 : ei0;
    int le = e - layer * NE;
    atomicAdd(&g_count[layer * NN + ei[NE + le]], 1);
}

// joint exclusive scan over g_count[0..TOTN): 3-phase multi-block scan
__global__ void scanA_kernel() {   // per-block reduce -> g_partial
    int i = blockIdx.x * 1024 + threadIdx.x;
    int v = (i < TOTN) ? g_count[i] : 0;
    #pragma unroll
    for (int o = 16; o > 0; o >>= 1) v += __shfl_down_sync(0xffffffffu, v, o);
    __shared__ int ws[32];
    if ((threadIdx.x & 31) == 0) ws[threadIdx.x >> 5] = v;
    __syncthreads();
    if (threadIdx.x < 32) {
        int t = ws[threadIdx.x];
        #pragma unroll
        for (int o = 16; o > 0; o >>= 1) t += __shfl_down_sync(0xffffffffu, t, o);
        if (threadIdx.x == 0) g_partial[blockIdx.x] = t;
    }
}

__global__ void scanB_kernel() {   // exclusive scan of the 98 partials (1 block)
    __shared__ int s[128];
    int tid = threadIdx.x;
    int v = (tid < NB) ? g_partial[tid] : 0;
    s[tid] = v;
    __syncthreads();
    #pragma unroll
    for (int o = 1; o < 128; o <<= 1) {
        int t = (tid >= o) ? s[tid - o] : 0;
        __syncthreads();
        s[tid] += t;
        __syncthreads();
    }
    if (tid < NB) g_partial[tid] = s[tid] - v;   // exclusive block offsets
}

__global__ void scanC_kernel() {   // block-local exclusive scan + offset -> start/cursor
    int tid = threadIdx.x;
    int i = blockIdx.x * 1024 + tid;
    int v = (i < TOTN) ? g_count[i] : 0;
    int lane = tid & 31, wid = tid >> 5;
    int incl = v;
    #pragma unroll
    for (int o = 1; o < 32; o <<= 1) {
        int y = __shfl_up_sync(0xffffffffu, incl, o);
        if (lane >= o) incl += y;
    }
    __shared__ int wsum[32];
    if (lane == 31) wsum[wid] = incl;
    __syncthreads();
    if (tid < 32) {
        int w = wsum[tid];
        #pragma unroll
        for (int o = 1; o < 32; o <<= 1) {
            int y = __shfl_up_sync(0xffffffffu, w, o);
            if (tid >= o) w += y;
        }
        wsum[tid] = w;
    }
    __syncthreads();
    int excl = incl - v + (wid ? wsum[wid - 1] : 0) + g_partial[blockIdx.x];
    if (i < TOTN) { g_start[i] = excl; g_cursor[i] = excl; }
    if (i == 0) g_start[TOTN] = TOTE;
}

__global__ void scatter_kernel(const int* __restrict__ ei0, const float* __restrict__ ea0,
                               const int* __restrict__ ei1, const float* __restrict__ ea1) {
    int e = blockIdx.x * blockDim.x + threadIdx.x;
    if (e >= TOTE) return;
    int layer = (e >= NE);
    const int*   ei = layer ? ei1 : ei0;
    const float* ea = layer ? ea1 : ea0;
    int le = e - layer * NE;
    int dst = ei[NE + le];
    int pos = atomicAdd(&g_cursor[layer * NN + dst], 1);
    g_src_sorted[pos] = ei[le];
    const float2* s = (const float2*)(ea + (size_t)le * 6);     // 24B stride -> 8B aligned
    float2* o = (float2*)(g_ea_sorted + (size_t)pos * 6);
    o[0] = s[0]; o[1] = s[1]; o[2] = s[2];
}

// ---------------- per-node edge aggregation (pull, no atomics) ----------------
// 64 threads per super-node (layer*NN+node); thread c owns channels 3c..3c+2
__global__ void __launch_bounds__(256) edge_aggr_kernel(
    const float* __restrict__ x,
    const float* __restrict__ Win0, const float* __restrict__ bin0,
    const float* __restrict__ Win1, const float* __restrict__ bin1)
{
    int nid = blockIdx.x * 4 + (threadIdx.x >> 6);   // 0..TOTN-1 (TOTN % 4 == 0)
    int c = threadIdx.x & 63;
    int layer = (nid >= NN);
    const float* W_in = layer ? Win1 : Win0;
    const float* b_in = layer ? bin1 : bin0;

    float w0[6], w1[6], w2[6];
    #pragma unroll
    for (int a = 0; a < 6; a++) {
        w0[a] = W_in[a * KDIM + 3 * c + 0];
        w1[a] = W_in[a * KDIM + 3 * c + 1];
        w2[a] = W_in[a * KDIM + 3 * c + 2];
    }
    float b0 = b_in[3 * c + 0], b1 = b_in[3 * c + 1], b2 = b_in[3 * c + 2];

    int s = g_start[nid], eEnd = g_start[nid + 1];

    float acc0 = 0.f, acc1 = 0.f, acc2 = 0.f;
    #pragma unroll 2
    for (int i = s; i < eEnd; i++) {
        int srcv = g_src_sorted[i];
        const float2* ea = (const float2*)(g_ea_sorted + (size_t)i * 6);
        float2 p0 = ea[0], p1 = ea[1], p2 = ea[2];
        float a0 = p0.x, a1 = p0.y, a2 = p1.x, a3 = p1.y, a4 = p2.x, a5 = p2.y;
        float xc = x[srcv * CIN + c];   // coalesced 256B gather, L2-resident

        float s0 = fmaf(a0, w0[0], b0); s0 = fmaf(a1, w0[1], s0); s0 = fmaf(a2, w0[2], s0);
        s0 = fmaf(a3, w0[3], s0); s0 = fmaf(a4, w0[4], s0); s0 = fmaf(a5, w0[5], s0);
        float s1 = fmaf(a0, w1[0], b1); s1 = fmaf(a1, w1[1], s1); s1 = fmaf(a2, w1[2], s1);
        s1 = fmaf(a3, w1[3], s1); s1 = fmaf(a4, w1[4], s1); s1 = fmaf(a5, w1[5], s1);
        float s2 = fmaf(a0, w2[0], b2); s2 = fmaf(a1, w2[1], s2); s2 = fmaf(a2, w2[2], s2);
        s2 = fmaf(a3, w2[3], s2); s2 = fmaf(a4, w2[4], s2); s2 = fmaf(a5, w2[5], s2);

        s0 = fmaxf(s0, 0.f); s1 = fmaxf(s1, 0.f); s2 = fmaxf(s2, 0.f);
        acc0 = fmaf(s0, xc, acc0);
        acc1 = fmaf(s1, xc, acc1);
        acc2 = fmaf(s2, xc, acc2);
    }

    float* o = g_aggr + (size_t)nid * KDIM + 3 * c;
    o[0] = acc0; o[1] = acc1; o[2] = acc2;
}

// ---------------- output GEMM + bias + tanh (f32x2 packed) ----------------
// block: 64 nodes x 128 cols, 256 threads; per thread 4 row-pairs x 4 cols.
// A tile stored transposed [kk][row] so a row-pair is one aligned LDS.64 (pre-packed).
__global__ void __launch_bounds__(256) gemm_tanh_kernel(
    const float* __restrict__ Wout0, const float* __restrict__ bout0,
    const float* __restrict__ Wout1, const float* __restrict__ bout1,
    float* __restrict__ out)
{
    int layer = blockIdx.y;
    const float* Wout = layer ? Wout1 : Wout0;
    const float* bout = layer ? bout1 : bout0;
    const float* aggr = g_aggr + (size_t)layer * NN * KDIM;

    __shared__ float As[32][66];    // [kk][row], row stride 66 keeps pairs 8B-aligned
    __shared__ float Bs[32][128];

    int tid = threadIdx.x;
    int tx = tid & 31;      // col lane
    int ty = tid >> 5;      // row group (0..7) -> rows ty*8 .. ty*8+7
    int n0 = blockIdx.x * 64;

    ull acc[4][4];          // [row-pair][col]; 0ull == (0.f, 0.f)
    #pragma unroll
    for (int p = 0; p < 4; p++)
        #pragma unroll
        for (int q = 0; q < 4; q++) acc[p][q] = 0ull;

    for (int k0 = 0; k0 < KDIM; k0 += 32) {
        #pragma unroll
        for (int j = 0; j < 8; j++) {
            int idx = tid + 256 * j;
            int r = idx >> 5, kk = idx & 31;
            int n = n0 + r;
            As[kk][r] = (n < NN) ? aggr[(size_t)n * KDIM + k0 + kk] : 0.f;
        }
        #pragma unroll
        for (int j = 0; j < 16; j++) {
            int idx = tid + 256 * j;
            int kk = idx >> 7, cc = idx & 127;
            Bs[kk][cc] = Wout[(k0 + kk) * COUT + cc];
        }
        __syncthreads();
        #pragma unroll
        for (int kk = 0; kk < 32; kk++) {
            ull a[4];
            #pragma unroll
            for (int p = 0; p < 4; p++)
                a[p] = *reinterpret_cast<const ull*>(&As[kk][ty * 8 + 2 * p]);  // broadcast LDS.64
            #pragma unroll
            for (int q = 0; q < 4; q++) {
                float b = Bs[kk][tx + 32 * q];
                ull bb = pack2(b, b);
                #pragma unroll
                for (int p = 0; p < 4; p++) fma2(acc[p][q], a[p], bb);
            }
        }
        __syncthreads();
    }

    #pragma unroll
    for (int q = 0; q < 4; q++) {
        int cc = tx + 32 * q;
        float bv = bout[cc];
        #pragma unroll
        for (int p = 0; p < 4; p++) {
            float lo, hi;
            unpack2(acc[p][q], lo, hi);
            int n = n0 + ty * 8 + 2 * p;
            if (n < NN)     out[(size_t)n * (2 * COUT) + (size_t)layer * COUT + cc]       = tanhf(lo + bv);
            if (n + 1 < NN) out[(size_t)(n + 1) * (2 * COUT) + (size_t)layer * COUT + cc] = tanhf(hi + bv);
        }
    }
}

extern "C" void kernel_launch(void* const* d_in, const int* in_sizes, int n_in,
                              void* d_out, int out_size) {
    const float* x     = (const float*)d_in[0];
    const int*   ei0   = (const int*)d_in[1];
    const float* ea0   = (const float*)d_in[2];
    const int*   ei1   = (const int*)d_in[3];
    const float* ea1   = (const float*)d_in[4];
    const float* Win0  = (const float*)d_in[5];
    const float* bin0  = (const float*)d_in[6];
    const float* Wout0 = (const float*)d_in[7];
    const float* bout0 = (const float*)d_in[8];
    const float* Win1  = (const float*)d_in[9];
    const float* bin1  = (const float*)d_in[10];
    const float* Wout1 = (const float*)d_in[11];
    const float* bout1 = (const float*)d_in[12];
    float* out = (float*)d_out;
    (void)in_sizes; (void)n_in; (void)out_size;

    zero_counts_kernel<<<(TOTN + 255) / 256, 256>>>();
    hist_kernel<<<(TOTE + 255) / 256, 256>>>(ei0, ei1);
    scanA_kernel<<<NB, 1024>>>();
    scanB_kernel<<<1, 128>>>();
    scanC_kernel<<<NB, 1024>>>();
    scatter_kernel<<<(TOTE + 255) / 256, 256>>>(ei0, ea0, ei1, ea1);

    edge_aggr_kernel<<<TOTN / 4, 256>>>(x, Win0, bin0, Win1, bin1);

    dim3 ggrid((NN + 63) / 64, 2);
    gemm_tanh_kernel<<<ggrid, 256>>>(Wout0, bout0, Wout1, bout1, out);
}